// round 2
// baseline (speedup 1.0000x reference)
#include <cuda_runtime.h>

#define B_SZ   8
#define C_IN   64
#define HW     1024
#define NHEADS 8

// Scratch (no allocations allowed): qkv activations and pre-projection attention out
__device__ float g_qkv[B_SZ * 192 * HW];   // [b][192][1024]; q(0-63,scaled), k(64-127), v(128-191)
__device__ float g_attn[B_SZ * 64 * HW];   // [b][64][1024]

// ---------------------------------------------------------------------------
// 3x3 conv, pad 1: out channels 0..63 of d_out ([b][128][1024] layout)
// grid (8 b, 16 ogroups of 4), block 256, 4 pixels/thread
// ---------------------------------------------------------------------------
__global__ __launch_bounds__(256) void conv3x3_kernel(
    const float* __restrict__ x, const float* __restrict__ w,
    const float* __restrict__ bias, float* __restrict__ out) {
  int b = blockIdx.x, og = blockIdx.y;
  __shared__ float xs[34 * 34];
  __shared__ float wsh[4 * 9];
  int t = threadIdx.x;
  float acc[4][4];
#pragma unroll
  for (int o = 0; o < 4; o++)
#pragma unroll
    for (int r = 0; r < 4; r++) acc[o][r] = 0.f;

  for (int c = 0; c < 64; c++) {
    __syncthreads();
    for (int i = t; i < 34 * 34; i += 256) {
      int yy = i / 34 - 1, xx = i % 34 - 1;
      float v = 0.f;
      if (yy >= 0 && yy < 32 && xx >= 0 && xx < 32)
        v = x[(b * 64 + c) * HW + yy * 32 + xx];
      xs[i] = v;
    }
    if (t < 36) wsh[t] = w[((og * 4 + t / 9) * 64 + c) * 9 + (t % 9)];
    __syncthreads();

    // hoist weights into registers once per c
    float wr[36];
#pragma unroll
    for (int i = 0; i < 36; i++) wr[i] = wsh[i];

#pragma unroll
    for (int r = 0; r < 4; r++) {
      int p = t + 256 * r;
      int py = p >> 5, px = p & 31;
      float v[9];
#pragma unroll
      for (int kh = 0; kh < 3; kh++)
#pragma unroll
        for (int kw = 0; kw < 3; kw++)
          v[kh * 3 + kw] = xs[(py + kh) * 34 + (px + kw)];
#pragma unroll
      for (int o = 0; o < 4; o++) {
        float a = acc[o][r];
#pragma unroll
        for (int k = 0; k < 9; k++) a += v[k] * wr[o * 9 + k];
        acc[o][r] = a;
      }
    }
  }
#pragma unroll
  for (int o = 0; o < 4; o++) {
    int oc = og * 4 + o;
    float bb = bias[oc];
#pragma unroll
    for (int r = 0; r < 4; r++) {
      int p = t + 256 * r;
      out[(b * 128 + oc) * HW + p] = acc[o][r] + bb;
    }
  }
}

// ---------------------------------------------------------------------------
// Pointwise (1x1) conv as tiled GEMM: 32 out-ch x 256 positions per block.
// 64 input channels. grid (b, og, ptile), block 256.
// Used for qkv projection (out=g_qkv, 192ch, q scaled) and output projection
// (out=d_out ch 64..127).
// ---------------------------------------------------------------------------
__global__ __launch_bounds__(256) void pw_gemm_kernel(
    const float* __restrict__ in,     // [b][64][1024]
    const float* __restrict__ w,      // [O][64]
    const float* __restrict__ bias,   // [O]
    float* __restrict__ out,          // [b][out_chans_b][1024]
    int out_chan_base, int out_chans_b, int qflag) {
  extern __shared__ float sm[];
  float* xs = sm;             // [64][256]
  float* ws = sm + 64 * 256;  // [64][32]
  int b = blockIdx.x, og = blockIdx.y, pt = blockIdx.z;
  int t = threadIdx.x;
  int p0 = pt * 256;

  for (int i = t; i < 64 * 256; i += 256) {
    int c = i >> 8, p = i & 255;
    xs[i] = in[(b * 64 + c) * HW + p0 + p];
  }
  for (int i = t; i < 64 * 32; i += 256) {
    int c = i >> 5, ol = i & 31;
    ws[i] = w[(og * 32 + ol) * 64 + c];
  }
  __syncthreads();

  int oi = t >> 5, pi = t & 31;
  float acc[4][8];
#pragma unroll
  for (int a = 0; a < 4; a++)
#pragma unroll
    for (int k = 0; k < 8; k++) acc[a][k] = 0.f;

  for (int c = 0; c < 64; c++) {
    float xv[8];
#pragma unroll
    for (int k = 0; k < 8; k++) xv[k] = xs[c * 256 + pi + 32 * k];
    float wv[4];
#pragma unroll
    for (int a = 0; a < 4; a++) wv[a] = ws[c * 32 + oi * 4 + a];
#pragma unroll
    for (int a = 0; a < 4; a++)
#pragma unroll
      for (int k = 0; k < 8; k++) acc[a][k] += wv[a] * xv[k];
  }

#pragma unroll
  for (int a = 0; a < 4; a++) {
    int o = og * 32 + oi * 4 + a;
    float bb = bias[o];
    float sc = (qflag && o < 64) ? 0.35355339059327373f : 1.f;  // dkh^-0.5
#pragma unroll
    for (int k = 0; k < 8; k++)
      out[(b * out_chans_b + out_chan_base + o) * HW + p0 + pi + 32 * k] =
          sc * (acc[a][k] + bb);
  }
}

// ---------------------------------------------------------------------------
// Attention: one (b, head) per blockIdx.x (64), row tiles per blockIdx.y (8).
// block = 256 (8 warps), warp handles 16 query rows; lane j-slice of 32.
// logits[i,j] = q_i.k_j + q_i.rel_w[w2-w1+31] + q_i.rel_h[h2-h1+31]
// With j = jj*32+lane: w2 = lane (own rw), h2 = jj (shfl of rh).
// ---------------------------------------------------------------------------
__global__ __launch_bounds__(256) void attn_kernel(
    const float* __restrict__ qkv,
    const float* __restrict__ relw,   // [63][8]
    const float* __restrict__ relh,   // [63][8]
    float* __restrict__ attn_out) {   // [b][64][1024]
  extern __shared__ float sm[];
  float4* k4 = (float4*)sm;            // [2][1024] : d0-3, d4-7
  float4* v4 = ((float4*)sm) + 2048;   // [2][1024]
  float* s_relw = sm + 16384;
  float* s_relh = s_relw + 63 * 8;

  int bn = blockIdx.x;
  int b = bn >> 3, n = bn & 7;
  int t = threadIdx.x, warp = t >> 5, lane = t & 31;

  const float* qb = qkv + (b * 192 + n * 8) * HW;
  const float* kb = qkv + (b * 192 + 64 + n * 8) * HW;
  const float* vb = qkv + (b * 192 + 128 + n * 8) * HW;

  // stage K, V into shared as float4 halves
#pragma unroll
  for (int g = 0; g < 4; g++) {
    const float* src = (g < 2 ? kb : vb) + (g & 1) * 4 * HW;
    float4* dst = (g < 2 ? k4 : v4) + (g & 1) * 1024;
    for (int j = t; j < 1024; j += 256) {
      float4 val;
      val.x = src[0 * HW + j];
      val.y = src[1 * HW + j];
      val.z = src[2 * HW + j];
      val.w = src[3 * HW + j];
      dst[j] = val;
    }
  }
  for (int i = t; i < 63 * 8; i += 256) {
    s_relw[i] = relw[i];
    s_relh[i] = relh[i];
  }
  __syncthreads();

  int row0 = blockIdx.y * 128 + warp * 16;
  for (int rr = 0; rr < 16; rr++) {
    int i = row0 + rr;
    int h1 = i >> 5, w1 = i & 31;

    float q0 = qb[0 * HW + i], q1 = qb[1 * HW + i], q2 = qb[2 * HW + i],
          q3 = qb[3 * HW + i], q4 = qb[4 * HW + i], q5 = qb[5 * HW + i],
          q6 = qb[6 * HW + i], q7 = qb[7 * HW + i];

    const float* rwp = s_relw + (lane - w1 + 31) * 8;
    float rw = q0 * rwp[0] + q1 * rwp[1] + q2 * rwp[2] + q3 * rwp[3] +
               q4 * rwp[4] + q5 * rwp[5] + q6 * rwp[6] + q7 * rwp[7];
    const float* rhp = s_relh + (lane - h1 + 31) * 8;
    float rh = q0 * rhp[0] + q1 * rhp[1] + q2 * rhp[2] + q3 * rhp[3] +
               q4 * rhp[4] + q5 * rhp[5] + q6 * rhp[6] + q7 * rhp[7];

    float l[32];
    float m = -1e30f;
#pragma unroll
    for (int jj = 0; jj < 32; jj++) {
      int j = jj * 32 + lane;
      float4 ka = k4[j], kbv = k4[1024 + j];
      float s = q0 * ka.x + q1 * ka.y + q2 * ka.z + q3 * ka.w +
                q4 * kbv.x + q5 * kbv.y + q6 * kbv.z + q7 * kbv.w;
      s += rw + __shfl_sync(0xffffffffu, rh, jj);
      l[jj] = s;
      m = fmaxf(m, s);
    }
#pragma unroll
    for (int off = 16; off; off >>= 1)
      m = fmaxf(m, __shfl_xor_sync(0xffffffffu, m, off));

    float ssum = 0.f;
    float a0 = 0, a1 = 0, a2 = 0, a3 = 0, a4 = 0, a5 = 0, a6 = 0, a7 = 0;
#pragma unroll
    for (int jj = 0; jj < 32; jj++) {
      int j = jj * 32 + lane;
      float p = __expf(l[jj] - m);
      ssum += p;
      float4 va = v4[j], vbv = v4[1024 + j];
      a0 += p * va.x;  a1 += p * va.y;  a2 += p * va.z;  a3 += p * va.w;
      a4 += p * vbv.x; a5 += p * vbv.y; a6 += p * vbv.z; a7 += p * vbv.w;
    }
#pragma unroll
    for (int off = 16; off; off >>= 1) {
      ssum += __shfl_xor_sync(0xffffffffu, ssum, off);
      a0 += __shfl_xor_sync(0xffffffffu, a0, off);
      a1 += __shfl_xor_sync(0xffffffffu, a1, off);
      a2 += __shfl_xor_sync(0xffffffffu, a2, off);
      a3 += __shfl_xor_sync(0xffffffffu, a3, off);
      a4 += __shfl_xor_sync(0xffffffffu, a4, off);
      a5 += __shfl_xor_sync(0xffffffffu, a5, off);
      a6 += __shfl_xor_sync(0xffffffffu, a6, off);
      a7 += __shfl_xor_sync(0xffffffffu, a7, off);
    }
    float inv = 1.f / ssum;
    float sel = a0;
    sel = (lane == 1) ? a1 : sel;
    sel = (lane == 2) ? a2 : sel;
    sel = (lane == 3) ? a3 : sel;
    sel = (lane == 4) ? a4 : sel;
    sel = (lane == 5) ? a5 : sel;
    sel = (lane == 6) ? a6 : sel;
    sel = (lane == 7) ? a7 : sel;
    if (lane < 8)
      attn_out[(b * 64 + n * 8 + lane) * HW + i] = sel * inv;
  }
}

// ---------------------------------------------------------------------------
extern "C" void kernel_launch(void* const* d_in, const int* in_sizes, int n_in,
                              void* d_out, int out_size) {
  (void)in_sizes; (void)n_in; (void)out_size;
  const float* x      = (const float*)d_in[0];
  const float* conv_w = (const float*)d_in[1];
  const float* conv_b = (const float*)d_in[2];
  const float* qkv_w  = (const float*)d_in[3];
  const float* qkv_b  = (const float*)d_in[4];
  const float* attn_w = (const float*)d_in[5];
  const float* attn_b = (const float*)d_in[6];
  const float* relw   = (const float*)d_in[7];
  const float* relh   = (const float*)d_in[8];
  float* out = (float*)d_out;

  float* qkv_s = nullptr;
  float* attn_s = nullptr;
  cudaGetSymbolAddress((void**)&qkv_s, g_qkv);
  cudaGetSymbolAddress((void**)&attn_s, g_attn);

  const int PW_SMEM = (64 * 256 + 64 * 32) * 4;      // 73728
  const int ATTN_SMEM = (16384 + 2 * 63 * 8) * 4;    // 69568
  cudaFuncSetAttribute(pw_gemm_kernel, cudaFuncAttributeMaxDynamicSharedMemorySize, PW_SMEM);
  cudaFuncSetAttribute(attn_kernel, cudaFuncAttributeMaxDynamicSharedMemorySize, ATTN_SMEM);

  // conv branch -> out channels 0..63
  conv3x3_kernel<<<dim3(8, 16), 256>>>(x, conv_w, conv_b, out);

  // qkv projection (q scaled by dkh^-0.5)
  pw_gemm_kernel<<<dim3(8, 6, 4), 256, PW_SMEM>>>(x, qkv_w, qkv_b, qkv_s, 0, 192, 1);

  // attention
  attn_kernel<<<dim3(64, 8), 256, ATTN_SMEM>>>(qkv_s, relw, relh, attn_s);

  // output projection -> out channels 64..127
  pw_gemm_kernel<<<dim3(8, 2, 4), 256, PW_SMEM>>>(attn_s, attn_w, attn_b, out, 64, 128, 0);
}

// round 3
// speedup vs baseline: 1.3711x; 1.3711x over previous
#include <cuda_runtime.h>

#define HW 1024

// Scratch: qkv activations (q pre-scaled by dkh^-0.5 * log2e) and attention out
__device__ float g_qkv[8 * 192 * HW];   // [b][192][1024]
__device__ float g_attn[8 * 64 * HW];   // [b][64][1024]

typedef unsigned long long u64;

__device__ __forceinline__ u64 fma2(u64 a, u64 b, u64 c) {
  u64 d; asm("fma.rn.f32x2 %0,%1,%2,%3;" : "=l"(d) : "l"(a), "l"(b), "l"(c)); return d;
}
__device__ __forceinline__ u64 add2(u64 a, u64 b) {
  u64 d; asm("add.rn.f32x2 %0,%1,%2;" : "=l"(d) : "l"(a), "l"(b)); return d;
}
__device__ __forceinline__ u64 pack2(float lo, float hi) {
  u64 d; asm("mov.b64 %0,{%1,%2};" : "=l"(d) : "f"(lo), "f"(hi)); return d;
}
__device__ __forceinline__ void unpack2(u64 v, float& lo, float& hi) {
  asm("mov.b64 {%0,%1},%2;" : "=f"(lo), "=f"(hi) : "l"(v));
}
__device__ __forceinline__ float ex2f(float x) {
  float y; asm("ex2.approx.ftz.f32 %0,%1;" : "=f"(y) : "f"(x)); return y;
}

// ---------------------------------------------------------------------------
// 3x3 conv, pad 1: out channels 0..63. grid (8 b, 16 og), block 256.
// ---------------------------------------------------------------------------
__global__ __launch_bounds__(256) void conv3x3_kernel(
    const float* __restrict__ x, const float* __restrict__ w,
    const float* __restrict__ bias, float* __restrict__ out) {
  int b = blockIdx.x, og = blockIdx.y;
  __shared__ float xs[34 * 34];
  __shared__ float wsh[4 * 9];
  int t = threadIdx.x;
  float acc[4][4];
#pragma unroll
  for (int o = 0; o < 4; o++)
#pragma unroll
    for (int r = 0; r < 4; r++) acc[o][r] = 0.f;

  for (int c = 0; c < 64; c++) {
    __syncthreads();
    for (int i = t; i < 34 * 34; i += 256) {
      int yy = i / 34 - 1, xx = i % 34 - 1;
      float v = 0.f;
      if (yy >= 0 && yy < 32 && xx >= 0 && xx < 32)
        v = x[(b * 64 + c) * HW + yy * 32 + xx];
      xs[i] = v;
    }
    if (t < 36) wsh[t] = w[((og * 4 + t / 9) * 64 + c) * 9 + (t % 9)];
    __syncthreads();

    float wr[36];
#pragma unroll
    for (int i = 0; i < 36; i++) wr[i] = wsh[i];

#pragma unroll
    for (int r = 0; r < 4; r++) {
      int p = t + 256 * r;
      int py = p >> 5, px = p & 31;
      float v[9];
#pragma unroll
      for (int kh = 0; kh < 3; kh++)
#pragma unroll
        for (int kw = 0; kw < 3; kw++)
          v[kh * 3 + kw] = xs[(py + kh) * 34 + (px + kw)];
#pragma unroll
      for (int o = 0; o < 4; o++) {
        float a = acc[o][r];
#pragma unroll
        for (int k = 0; k < 9; k++) a += v[k] * wr[o * 9 + k];
        acc[o][r] = a;
      }
    }
  }
#pragma unroll
  for (int o = 0; o < 4; o++) {
    int oc = og * 4 + o;
    float bb = bias[oc];
#pragma unroll
    for (int r = 0; r < 4; r++)
      out[(b * 128 + oc) * HW + t + 256 * r] = acc[o][r] + bb;
  }
}

// ---------------------------------------------------------------------------
// 1x1 conv as GEMM, f32x2: 32 out-ch x 128 positions per block, block 256.
// grid (b, O/32, 8). qflag scales q channels (o<64) by dkh^-0.5 * log2e.
// ---------------------------------------------------------------------------
__global__ __launch_bounds__(256) void pw_gemm_kernel(
    const float* __restrict__ in, const float* __restrict__ w,
    const float* __restrict__ bias, float* __restrict__ out,
    int out_chan_base, int out_chans_b, int qflag) {
  extern __shared__ char smraw[];
  float* xs = (float*)smraw;                 // [64][128]  32KB
  u64* ws2 = (u64*)(smraw + 64 * 128 * 4);   // [64][32]   16KB
  int b = blockIdx.x, og = blockIdx.y, pt = blockIdx.z;
  int t = threadIdx.x;
  int p0 = pt * 128;

  for (int i = t; i < 64 * 128; i += 256) {
    int c = i >> 7, pp = i & 127;
    xs[i] = in[(b * 64 + c) * HW + p0 + pp];
  }
  for (int i = t; i < 64 * 32; i += 256) {
    int c = i >> 5, o = i & 31;
    float wv = w[(og * 32 + o) * 64 + c];
    ws2[i] = pack2(wv, wv);
  }
  __syncthreads();

  int oi = t >> 5, pi = t & 31;   // oi: 4-och group, pi: pos-pair lane
  u64 acc2[4][2];
#pragma unroll
  for (int a = 0; a < 4; a++) { acc2[a][0] = 0ull; acc2[a][1] = 0ull; }

  for (int c = 0; c < 64; c++) {
    u64 xv0 = *(const u64*)(xs + c * 128 + pi * 2);
    u64 xv1 = *(const u64*)(xs + c * 128 + 64 + pi * 2);
    u64 wv[4];
#pragma unroll
    for (int a = 0; a < 4; a++) wv[a] = ws2[c * 32 + oi * 4 + a];
#pragma unroll
    for (int a = 0; a < 4; a++) {
      acc2[a][0] = fma2(wv[a], xv0, acc2[a][0]);
      acc2[a][1] = fma2(wv[a], xv1, acc2[a][1]);
    }
  }

#pragma unroll
  for (int a = 0; a < 4; a++) {
    int o = og * 32 + oi * 4 + a;
    float bb = bias[o];
    float sc = (qflag && o < 64) ? (0.35355339059327373f * 1.4426950408889634f) : 1.f;
    float* ob = out + (b * out_chans_b + out_chan_base + o) * HW + p0;
#pragma unroll
    for (int k = 0; k < 2; k++) {
      float lo, hi; unpack2(acc2[a][k], lo, hi);
      float2 v = make_float2(sc * (lo + bb), sc * (hi + bb));
      *(float2*)(ob + 64 * k + pi * 2) = v;
    }
  }
}

// ---------------------------------------------------------------------------
// Attention, f32x2 packed over row pairs. grid (64 bn, 2 halves), block 256.
// Each thread owns rows (i0, i0+1); K/V staged duplicated in shared;
// logits[i,j] = q.k_j + rwT[w2] + rh(h2); single-pass softmax (no max, q
// pre-scaled by log2e so exp == ex2).
// ---------------------------------------------------------------------------
#define AT_KD    0
#define AT_VD    65536
#define AT_RWT   131072                 // 256 pairs * 33 u64
#define AT_RELW  (AT_RWT + 256*33*8)    // 63*8 floats
#define AT_RELHD (AT_RELW + 2048)       // 63*8 u64 (dup)
#define AT_SMEM  (AT_RELHD + 63*8*8)

__global__ __launch_bounds__(256) void attn_kernel(
    const float* __restrict__ qkv,
    const float* __restrict__ relw, const float* __restrict__ relh,
    float* __restrict__ attn_out) {
  extern __shared__ char sm[];
  int t = threadIdx.x;
  int bn = blockIdx.x;
  int b = bn >> 3, n = bn & 7;
  int half = blockIdx.y;

  const float* qb = qkv + (b * 192 + n * 8) * HW;
  const float* kb = qkv + (b * 192 + 64 + n * 8) * HW;
  const float* vb = qkv + (b * 192 + 128 + n * 8) * HW;

  // stage K,V duplicated: entry e -> j=e>>3, d=e&7, value (k,k)
  for (int e = t; e < 8192; e += 256) {
    int j = e >> 3, d = e & 7;
    float kv = kb[d * HW + j];
    float vv = vb[d * HW + j];
    *(u64*)(sm + AT_KD + e * 8) = pack2(kv, kv);
    *(u64*)(sm + AT_VD + e * 8) = pack2(vv, vv);
  }
  float* s_relw = (float*)(sm + AT_RELW);
  for (int e = t; e < 504; e += 256) {
    s_relw[e] = relw[e];
    float rv = relh[e];
    *(u64*)(sm + AT_RELHD + e * 8) = pack2(rv, rv);
  }
  __syncthreads();

  // this thread's row pair
  int p = t;                       // pair id 0..255
  int i0 = half * 512 + 2 * p;     // global rows i0, i0+1
  int h1 = i0 >> 5, w1 = i0 & 31;  // i0 even -> w1<=30, same h1 for both rows

  float qlo[8], qhi[8];
  u64 q2[8];
#pragma unroll
  for (int d = 0; d < 8; d++) {
    qlo[d] = qb[d * HW + i0];
    qhi[d] = qb[d * HW + i0 + 1];
    q2[d] = pack2(qlo[d], qhi[d]);
  }

  // build rw table for this pair (own slot only; no sync needed)
  u64* rwrow = (u64*)(sm + AT_RWT) + p * 33;
  for (int w2 = 0; w2 < 32; w2++) {
    const float* r0 = s_relw + (w2 - w1 + 31) * 8;
    const float* r1 = r0 - 8;  // w1+1
    float a = 0.f, c = 0.f;
#pragma unroll
    for (int d = 0; d < 8; d++) { a += qlo[d] * r0[d]; c += qhi[d] * r1[d]; }
    rwrow[w2] = pack2(a, c);
  }

  u64 acc[8], ssum = 0ull;
#pragma unroll
  for (int d = 0; d < 8; d++) acc[d] = 0ull;

  const char* kbase = sm + AT_KD;
  const char* vbase = sm + AT_VD;

  for (int h2 = 0; h2 < 32; h2++) {
    const u64* rhp = (const u64*)(sm + AT_RELHD) + (h2 - h1 + 31) * 8;
    u64 rh2 = 0ull;
#pragma unroll
    for (int d = 0; d < 8; d++) rh2 = fma2(q2[d], rhp[d], rh2);

#pragma unroll 4
    for (int w2 = 0; w2 < 32; w2++) {
      int j = h2 * 32 + w2;
      const ulonglong2* kj = (const ulonglong2*)(kbase + j * 64);
      ulonglong2 k0 = kj[0], k1 = kj[1], k2 = kj[2], k3 = kj[3];
      u64 s2 = add2(rwrow[w2], rh2);
      s2 = fma2(q2[0], k0.x, s2); s2 = fma2(q2[1], k0.y, s2);
      s2 = fma2(q2[2], k1.x, s2); s2 = fma2(q2[3], k1.y, s2);
      s2 = fma2(q2[4], k2.x, s2); s2 = fma2(q2[5], k2.y, s2);
      s2 = fma2(q2[6], k3.x, s2); s2 = fma2(q2[7], k3.y, s2);
      float slo, shi; unpack2(s2, slo, shi);
      u64 p2 = pack2(ex2f(slo), ex2f(shi));
      ssum = add2(ssum, p2);
      const ulonglong2* vj = (const ulonglong2*)(vbase + j * 64);
      ulonglong2 v0 = vj[0], v1 = vj[1], v2 = vj[2], v3 = vj[3];
      acc[0] = fma2(p2, v0.x, acc[0]); acc[1] = fma2(p2, v0.y, acc[1]);
      acc[2] = fma2(p2, v1.x, acc[2]); acc[3] = fma2(p2, v1.y, acc[3]);
      acc[4] = fma2(p2, v2.x, acc[4]); acc[5] = fma2(p2, v2.y, acc[5]);
      acc[6] = fma2(p2, v3.x, acc[6]); acc[7] = fma2(p2, v3.y, acc[7]);
    }
  }

  float slo, shi; unpack2(ssum, slo, shi);
  float ilo = 1.f / slo, ihi = 1.f / shi;
  float* ob = attn_out + (b * 64 + n * 8) * HW + i0;
#pragma unroll
  for (int d = 0; d < 8; d++) {
    float alo, ahi; unpack2(acc[d], alo, ahi);
    *(float2*)(ob + d * HW) = make_float2(alo * ilo, ahi * ihi);
  }
}

// ---------------------------------------------------------------------------
extern "C" void kernel_launch(void* const* d_in, const int* in_sizes, int n_in,
                              void* d_out, int out_size) {
  (void)in_sizes; (void)n_in; (void)out_size;
  const float* x      = (const float*)d_in[0];
  const float* conv_w = (const float*)d_in[1];
  const float* conv_b = (const float*)d_in[2];
  const float* qkv_w  = (const float*)d_in[3];
  const float* qkv_b  = (const float*)d_in[4];
  const float* attn_w = (const float*)d_in[5];
  const float* attn_b = (const float*)d_in[6];
  const float* relw   = (const float*)d_in[7];
  const float* relh   = (const float*)d_in[8];
  float* out = (float*)d_out;

  float* qkv_s = nullptr;
  float* attn_s = nullptr;
  cudaGetSymbolAddress((void**)&qkv_s, g_qkv);
  cudaGetSymbolAddress((void**)&attn_s, g_attn);

  const int PW_SMEM = 64 * 128 * 4 + 64 * 32 * 8;  // 48KB
  cudaFuncSetAttribute(pw_gemm_kernel, cudaFuncAttributeMaxDynamicSharedMemorySize, PW_SMEM);
  cudaFuncSetAttribute(attn_kernel, cudaFuncAttributeMaxDynamicSharedMemorySize, AT_SMEM);

  // conv branch -> out channels 0..63
  conv3x3_kernel<<<dim3(8, 16), 256>>>(x, conv_w, conv_b, out);

  // qkv projection (q channels scaled by dkh^-0.5 * log2e)
  pw_gemm_kernel<<<dim3(8, 6, 8), 256, PW_SMEM>>>(x, qkv_w, qkv_b, qkv_s, 0, 192, 1);

  // attention
  attn_kernel<<<dim3(64, 2), 256, AT_SMEM>>>(qkv_s, relw, relh, attn_s);

  // output projection -> out channels 64..127
  pw_gemm_kernel<<<dim3(8, 2, 8), 256, PW_SMEM>>>(attn_s, attn_w, attn_b, out, 64, 128, 0);
}

// round 4
// speedup vs baseline: 1.6178x; 1.1800x over previous
#include <cuda_runtime.h>

#define HW 1024

// Scratch buffers
__device__ float g_qkv[8 * 192 * HW];        // [b][192][1024]; q pre-scaled by dkh^-0.5*log2e
__device__ float g_pacc[2 * 8 * 64 * HW];    // [whalf][b][64][1024] partial softmax-weighted V sums
__device__ float g_pssum[2 * 8 * 8 * HW];    // [whalf][b][n][1024] partial exp sums

typedef unsigned long long u64;

__device__ __forceinline__ u64 fma2(u64 a, u64 b, u64 c) {
  u64 d; asm("fma.rn.f32x2 %0,%1,%2,%3;" : "=l"(d) : "l"(a), "l"(b), "l"(c)); return d;
}
__device__ __forceinline__ u64 add2(u64 a, u64 b) {
  u64 d; asm("add.rn.f32x2 %0,%1,%2;" : "=l"(d) : "l"(a), "l"(b)); return d;
}
__device__ __forceinline__ u64 pack2(float lo, float hi) {
  u64 d; asm("mov.b64 %0,{%1,%2};" : "=l"(d) : "f"(lo), "f"(hi)); return d;
}
__device__ __forceinline__ void unpack2(u64 v, float& lo, float& hi) {
  asm("mov.b64 {%0,%1},%2;" : "=f"(lo), "=f"(hi) : "l"(v));
}
__device__ __forceinline__ float ex2f(float x) {
  float y; asm("ex2.approx.ftz.f32 %0,%1;" : "=f"(y) : "f"(x)); return y;
}

// ---------------------------------------------------------------------------
// Fused prep: blocks [0,128) do 3x3 conv (out ch 0..63); blocks [128,512) do
// the qkv 1x1 projection into g_qkv. 256 threads, <=48KB smem -> 4 blocks/SM.
// ---------------------------------------------------------------------------
__global__ __launch_bounds__(256) void prep_kernel(
    const float* __restrict__ x,
    const float* __restrict__ conv_w, const float* __restrict__ conv_b,
    const float* __restrict__ qkv_w, const float* __restrict__ qkv_b,
    float* __restrict__ out, float* __restrict__ qkv_out) {
  extern __shared__ char smraw[];
  int blk = blockIdx.x;
  int t = threadIdx.x;

  if (blk < 128) {
    // ---------------- conv 3x3, pad 1 ----------------
    float* xs = (float*)smraw;          // [8][1156]  (34x34 halo planes)
    float* wsh = (float*)smraw + 9248;  // [2304] all weights for this og
    int b = blk >> 4, og = blk & 15;

    const float* wog = conv_w + og * 2304;  // 4 oc x 64 c x 9, contiguous
    for (int i = t; i < 2304; i += 256) wsh[i] = wog[i];

    float acc[4][4];
#pragma unroll
    for (int o = 0; o < 4; o++)
#pragma unroll
      for (int r = 0; r < 4; r++) acc[o][r] = 0.f;

    for (int c0 = 0; c0 < 64; c0 += 8) {
      __syncthreads();
      for (int i = t; i < 9248; i += 256) {
        int cc = i / 1156, rr = i - cc * 1156;
        int yy = rr / 34 - 1, xx = rr % 34 - 1;
        float v = 0.f;
        if (yy >= 0 && yy < 32 && xx >= 0 && xx < 32)
          v = x[(b * 64 + c0 + cc) * HW + yy * 32 + xx];
        xs[i] = v;
      }
      __syncthreads();

      for (int cc = 0; cc < 8; cc++) {
        const float* xc = xs + cc * 1156;
        float wr[36];
#pragma unroll
        for (int i = 0; i < 36; i++)
          wr[i] = wsh[(i / 9) * 576 + (c0 + cc) * 9 + (i % 9)];
#pragma unroll
        for (int r = 0; r < 4; r++) {
          int p = t + 256 * r;
          int py = p >> 5, px = p & 31;
          float v[9];
#pragma unroll
          for (int kh = 0; kh < 3; kh++)
#pragma unroll
            for (int kw = 0; kw < 3; kw++)
              v[kh * 3 + kw] = xc[(py + kh) * 34 + (px + kw)];
#pragma unroll
          for (int o = 0; o < 4; o++) {
            float a = acc[o][r];
#pragma unroll
            for (int k = 0; k < 9; k++) a += v[k] * wr[o * 9 + k];
            acc[o][r] = a;
          }
        }
      }
    }
#pragma unroll
    for (int o = 0; o < 4; o++) {
      int oc = og * 4 + o;
      float bb = conv_b[oc];
#pragma unroll
      for (int r = 0; r < 4; r++)
        out[(b * 128 + oc) * HW + t + 256 * r] = acc[o][r] + bb;
    }
  } else {
    // ---------------- qkv 1x1 projection ----------------
    float* xs = (float*)smraw;               // [64][128] 32KB
    u64* ws2 = (u64*)(smraw + 32768);        // [64][32]  16KB
    int r = blk - 128;
    int b = r / 48;
    int rem = r - b * 48;
    int og = rem >> 3, pt = rem & 7;
    int p0 = pt * 128;

    for (int i = t; i < 64 * 128; i += 256) {
      int c = i >> 7, pp = i & 127;
      xs[i] = x[(b * 64 + c) * HW + p0 + pp];
    }
    for (int i = t; i < 64 * 32; i += 256) {
      int c = i >> 5, o = i & 31;
      float wv = qkv_w[(og * 32 + o) * 64 + c];
      ws2[i] = pack2(wv, wv);
    }
    __syncthreads();

    int oi = t >> 5, pi = t & 31;
    u64 acc2[4][2];
#pragma unroll
    for (int a = 0; a < 4; a++) { acc2[a][0] = 0ull; acc2[a][1] = 0ull; }

    for (int c0 = 0; c0 < 64; c0 += 4) {
      u64 xv[4][2], wv[4][4];
#pragma unroll
      for (int cc = 0; cc < 4; cc++) {
        xv[cc][0] = *(const u64*)(xs + (c0 + cc) * 128 + pi * 2);
        xv[cc][1] = *(const u64*)(xs + (c0 + cc) * 128 + 64 + pi * 2);
      }
#pragma unroll
      for (int cc = 0; cc < 4; cc++)
#pragma unroll
        for (int a = 0; a < 4; a++) wv[cc][a] = ws2[(c0 + cc) * 32 + oi * 4 + a];
#pragma unroll
      for (int cc = 0; cc < 4; cc++)
#pragma unroll
        for (int a = 0; a < 4; a++) {
          acc2[a][0] = fma2(wv[cc][a], xv[cc][0], acc2[a][0]);
          acc2[a][1] = fma2(wv[cc][a], xv[cc][1], acc2[a][1]);
        }
    }

#pragma unroll
    for (int a = 0; a < 4; a++) {
      int o = og * 32 + oi * 4 + a;
      float bb = qkv_b[o];
      float sc = (o < 64) ? (0.35355339059327373f * 1.4426950408889634f) : 1.f;
      float* ob = qkv_out + (b * 192 + o) * HW + p0;
#pragma unroll
      for (int k = 0; k < 2; k++) {
        float lo, hi; unpack2(acc2[a][k], lo, hi);
        *(float2*)(ob + 64 * k + pi * 2) = make_float2(sc * (lo + bb), sc * (hi + bb));
      }
    }
  }
}

// ---------------------------------------------------------------------------
// Attention partials. grid (64 bn, 2 rowhalf, 2 whalf), block 256.
// Thread owns row pair (i0,i0+1); block covers j's with w2 in its half.
// Writes partial exp-sums and exp-weighted V sums; proj merges + divides.
// ---------------------------------------------------------------------------
#define AT_KD    0
#define AT_VD    32768
#define AT_RWT   65536                   // 256 pairs * 17 u64 = 34816
#define AT_RELW  (65536 + 34816)         // 504 floats
#define AT_RELHD (AT_RELW + 2016)        // 504 u64
#define AT_SMEM  (AT_RELHD + 4032)       // 106400 bytes -> 2 blocks/SM

__global__ __launch_bounds__(256) void attn_kernel(
    const float* __restrict__ qkv,
    const float* __restrict__ relw, const float* __restrict__ relh,
    float* __restrict__ pacc, float* __restrict__ pssum) {
  extern __shared__ char sm[];
  int t = threadIdx.x;
  int bn = blockIdx.x;
  int b = bn >> 3, n = bn & 7;
  int rowhalf = blockIdx.y;
  int whalf = blockIdx.z;

  const float* qb = qkv + (b * 192 + n * 8) * HW;
  const float* kb = qkv + (b * 192 + 64 + n * 8) * HW;
  const float* vb = qkv + (b * 192 + 128 + n * 8) * HW;

  // stage this w-half of K,V duplicated: jl = h2*16 + w2l
  u64* kdup = (u64*)(sm + AT_KD);
  u64* vdup = (u64*)(sm + AT_VD);
  for (int e = t; e < 4096; e += 256) {
    int jl = e >> 3, d = e & 7;
    int h2 = jl >> 4, w2l = jl & 15;
    int j = h2 * 32 + whalf * 16 + w2l;
    float kv = kb[d * HW + j];
    float vv = vb[d * HW + j];
    kdup[jl * 8 + d] = pack2(kv, kv);
    vdup[jl * 8 + d] = pack2(vv, vv);
  }
  float* s_relw = (float*)(sm + AT_RELW);
  for (int e = t; e < 504; e += 256) {
    s_relw[e] = relw[e];
    float rv = relh[e];
    *(u64*)(sm + AT_RELHD + e * 8) = pack2(rv, rv);
  }
  __syncthreads();

  int p = t;
  int i0 = rowhalf * 512 + 2 * p;
  int h1 = i0 >> 5, w1 = i0 & 31;   // even i0: rows share h1

  float qlo[8], qhi[8];
  u64 q2[8];
#pragma unroll
  for (int d = 0; d < 8; d++) {
    qlo[d] = qb[d * HW + i0];
    qhi[d] = qb[d * HW + i0 + 1];
    q2[d] = pack2(qlo[d], qhi[d]);
  }

  // per-pair rw table for this w-half
  u64* rwrow = (u64*)(sm + AT_RWT) + p * 17;
  for (int w2l = 0; w2l < 16; w2l++) {
    int w2 = whalf * 16 + w2l;
    const float* r0 = s_relw + (w2 - w1 + 31) * 8;
    const float* r1 = r0 - 8;
    float a = 0.f, c = 0.f;
#pragma unroll
    for (int d = 0; d < 8; d++) { a += qlo[d] * r0[d]; c += qhi[d] * r1[d]; }
    rwrow[w2l] = pack2(a, c);
  }

  u64 acc[8], ssum = 0ull;
#pragma unroll
  for (int d = 0; d < 8; d++) acc[d] = 0ull;

  for (int h2 = 0; h2 < 32; h2++) {
    const u64* rhp = (const u64*)(sm + AT_RELHD) + (h2 - h1 + 31) * 8;
    u64 rh2 = 0ull;
#pragma unroll
    for (int d = 0; d < 8; d++) rh2 = fma2(q2[d], rhp[d], rh2);

#pragma unroll 4
    for (int w2l = 0; w2l < 16; w2l++) {
      int jl = h2 * 16 + w2l;
      const ulonglong2* kj = (const ulonglong2*)(kdup + jl * 8);
      ulonglong2 k0 = kj[0], k1 = kj[1], k2 = kj[2], k3 = kj[3];
      u64 s2 = add2(rwrow[w2l], rh2);
      s2 = fma2(q2[0], k0.x, s2); s2 = fma2(q2[1], k0.y, s2);
      s2 = fma2(q2[2], k1.x, s2); s2 = fma2(q2[3], k1.y, s2);
      s2 = fma2(q2[4], k2.x, s2); s2 = fma2(q2[5], k2.y, s2);
      s2 = fma2(q2[6], k3.x, s2); s2 = fma2(q2[7], k3.y, s2);
      float slo, shi; unpack2(s2, slo, shi);
      u64 p2 = pack2(ex2f(slo), ex2f(shi));
      ssum = add2(ssum, p2);
      const ulonglong2* vj = (const ulonglong2*)(vdup + jl * 8);
      ulonglong2 v0 = vj[0], v1 = vj[1], v2 = vj[2], v3 = vj[3];
      acc[0] = fma2(p2, v0.x, acc[0]); acc[1] = fma2(p2, v0.y, acc[1]);
      acc[2] = fma2(p2, v1.x, acc[2]); acc[3] = fma2(p2, v1.y, acc[3]);
      acc[4] = fma2(p2, v2.x, acc[4]); acc[5] = fma2(p2, v2.y, acc[5]);
      acc[6] = fma2(p2, v3.x, acc[6]); acc[7] = fma2(p2, v3.y, acc[7]);
    }
  }

  float slo, shi; unpack2(ssum, slo, shi);
  *(float2*)(pssum + ((whalf * 8 + b) * 8 + n) * HW + i0) = make_float2(slo, shi);
  float* ab = pacc + ((whalf * 8 + b) * 64 + n * 8) * HW + i0;
#pragma unroll
  for (int d = 0; d < 8; d++) {
    float alo, ahi; unpack2(acc[d], alo, ahi);
    *(float2*)(ab + d * HW) = make_float2(alo, ahi);
  }
}

// ---------------------------------------------------------------------------
// Output projection with fused partial merge + softmax division.
// grid (8 b, 2 og, 8 pt), block 256. Writes out channels 64..127.
// ---------------------------------------------------------------------------
__global__ __launch_bounds__(256) void proj_kernel(
    const float* __restrict__ pacc, const float* __restrict__ pssum,
    const float* __restrict__ w, const float* __restrict__ bias,
    float* __restrict__ out) {
  extern __shared__ char smraw[];
  float* invs = (float*)smraw;                     // [8][128] 4KB
  float* xs = (float*)(smraw + 4096);              // [64][128] 32KB
  u64* ws2 = (u64*)(smraw + 4096 + 32768);         // [64][32] 16KB
  int b = blockIdx.x, og = blockIdx.y, pt = blockIdx.z;
  int t = threadIdx.x;
  int p0 = pt * 128;

  for (int i = t; i < 1024; i += 256) {
    int n = i >> 7, pp = i & 127;
    float s = pssum[(b * 8 + n) * HW + p0 + pp] +
              pssum[(64 + b * 8 + n) * HW + p0 + pp];
    invs[i] = 1.f / s;
  }
  for (int i = t; i < 64 * 32; i += 256) {
    int c = i >> 5, o = i & 31;
    float wv = w[(og * 32 + o) * 64 + c];
    ws2[i] = pack2(wv, wv);
  }
  __syncthreads();
  for (int i = t; i < 64 * 128; i += 256) {
    int c = i >> 7, pp = i & 127;
    int idx = (b * 64 + c) * HW + p0 + pp;
    xs[i] = (pacc[idx] + pacc[idx + 512 * HW]) * invs[(c >> 3) * 128 + pp];
  }
  __syncthreads();

  int oi = t >> 5, pi = t & 31;
  u64 acc2[4][2];
#pragma unroll
  for (int a = 0; a < 4; a++) { acc2[a][0] = 0ull; acc2[a][1] = 0ull; }

  for (int c0 = 0; c0 < 64; c0 += 4) {
    u64 xv[4][2], wv[4][4];
#pragma unroll
    for (int cc = 0; cc < 4; cc++) {
      xv[cc][0] = *(const u64*)(xs + (c0 + cc) * 128 + pi * 2);
      xv[cc][1] = *(const u64*)(xs + (c0 + cc) * 128 + 64 + pi * 2);
    }
#pragma unroll
    for (int cc = 0; cc < 4; cc++)
#pragma unroll
      for (int a = 0; a < 4; a++) wv[cc][a] = ws2[(c0 + cc) * 32 + oi * 4 + a];
#pragma unroll
    for (int cc = 0; cc < 4; cc++)
#pragma unroll
      for (int a = 0; a < 4; a++) {
        acc2[a][0] = fma2(wv[cc][a], xv[cc][0], acc2[a][0]);
        acc2[a][1] = fma2(wv[cc][a], xv[cc][1], acc2[a][1]);
      }
  }

#pragma unroll
  for (int a = 0; a < 4; a++) {
    int o = og * 32 + oi * 4 + a;
    float bb = bias[o];
    float* ob = out + (b * 128 + 64 + o) * HW + p0;
#pragma unroll
    for (int k = 0; k < 2; k++) {
      float lo, hi; unpack2(acc2[a][k], lo, hi);
      *(float2*)(ob + 64 * k + pi * 2) = make_float2(lo + bb, hi + bb);
    }
  }
}

// ---------------------------------------------------------------------------
extern "C" void kernel_launch(void* const* d_in, const int* in_sizes, int n_in,
                              void* d_out, int out_size) {
  (void)in_sizes; (void)n_in; (void)out_size;
  const float* x      = (const float*)d_in[0];
  const float* conv_w = (const float*)d_in[1];
  const float* conv_b = (const float*)d_in[2];
  const float* qkv_w  = (const float*)d_in[3];
  const float* qkv_b  = (const float*)d_in[4];
  const float* attn_w = (const float*)d_in[5];
  const float* attn_b = (const float*)d_in[6];
  const float* relw   = (const float*)d_in[7];
  const float* relh   = (const float*)d_in[8];
  float* out = (float*)d_out;

  float *qkv_s = nullptr, *pacc = nullptr, *pssum = nullptr;
  cudaGetSymbolAddress((void**)&qkv_s, g_qkv);
  cudaGetSymbolAddress((void**)&pacc, g_pacc);
  cudaGetSymbolAddress((void**)&pssum, g_pssum);

  const int PREP_SMEM = 49152;
  const int PROJ_SMEM = 4096 + 32768 + 16384;
  cudaFuncSetAttribute(prep_kernel, cudaFuncAttributeMaxDynamicSharedMemorySize, PREP_SMEM);
  cudaFuncSetAttribute(attn_kernel, cudaFuncAttributeMaxDynamicSharedMemorySize, AT_SMEM);
  cudaFuncSetAttribute(proj_kernel, cudaFuncAttributeMaxDynamicSharedMemorySize, PROJ_SMEM);

  prep_kernel<<<512, 256, PREP_SMEM>>>(x, conv_w, conv_b, qkv_w, qkv_b, out, qkv_s);
  attn_kernel<<<dim3(64, 2, 2), 256, AT_SMEM>>>(qkv_s, relw, relh, pacc, pssum);
  proj_kernel<<<dim3(8, 2, 8), 256, PROJ_SMEM>>>(pacc, pssum, attn_w, attn_b, out);
}